// round 4
// baseline (speedup 1.0000x reference)
#include <cuda_runtime.h>
#include <math.h>

#define N_TOK 2048
#define D_DIM 1024
#define H_DIM 4096
#define E_NUM 8
#define R_DIM 16
#define LSCALE 2.0f   // lora_alpha / lora_r = 32/16
#define NSLOT (2*N_TOK)

// ---------------- scratch (device globals; no allocation allowed) ----------------
__device__ float g_common[N_TOK * H_DIM];
__device__ float g_act[NSLOT * H_DIM];
__device__ float g_base2[NSLOT * D_DIM];
__device__ float g_t1[NSLOT * R_DIM];
__device__ float g_t2[NSLOT * R_DIM];
__device__ int   g_sel[NSLOT];
__device__ float g_wt[NSLOT];
// expert-grouped dispatch
__device__ int g_cnt[E_NUM];
__device__ int g_off[E_NUM];
__device__ int g_pos[E_NUM];
__device__ int g_list[NSLOT];

// ---------------- router ----------------
__global__ void router_kernel(const float* __restrict__ x, const float* __restrict__ gate) {
    int t = blockIdx.x;
    int warp = threadIdx.x >> 5, lane = threadIdx.x & 31;
    __shared__ float logits[E_NUM];
    const float4* xr = (const float4*)(x + (size_t)t * D_DIM);
    const float4* gr = (const float4*)(gate + (size_t)warp * D_DIM);
    float s = 0.f;
    for (int i = lane; i < D_DIM / 4; i += 32) {
        float4 a = xr[i], b = gr[i];
        s += a.x * b.x + a.y * b.y + a.z * b.z + a.w * b.w;
    }
    #pragma unroll
    for (int o = 16; o; o >>= 1) s += __shfl_xor_sync(0xffffffffu, s, o);
    if (lane == 0) logits[warp] = s;
    __syncthreads();
    if (threadIdx.x == 0) {
        float best = -1e30f; int i0 = 0;
        #pragma unroll
        for (int e = 0; e < E_NUM; e++) if (logits[e] > best) { best = logits[e]; i0 = e; }
        float best2 = -1e30f; int i1 = 0;
        #pragma unroll
        for (int e = 0; e < E_NUM; e++) if (e != i0 && logits[e] > best2) { best2 = logits[e]; i1 = e; }
        float p1 = expf(best2 - best);
        float inv = 1.f / (1.f + p1);
        g_sel[t * 2 + 0] = i0; g_sel[t * 2 + 1] = i1;
        g_wt[t * 2 + 0] = inv; g_wt[t * 2 + 1] = p1 * inv;
    }
}

// ---------------- dispatch: count / prefix / scatter ----------------
__global__ void dispatch_zero() {
    if (threadIdx.x < E_NUM) g_cnt[threadIdx.x] = 0;
}
__global__ void dispatch_count() {
    int i = blockIdx.x * 256 + threadIdx.x;
    if (i < NSLOT) atomicAdd(&g_cnt[g_sel[i]], 1);
}
__global__ void dispatch_prefix() {
    if (threadIdx.x == 0) {
        int o = 0;
        for (int e = 0; e < E_NUM; e++) { g_off[e] = o; g_pos[e] = o; o += g_cnt[e]; }
    }
}
__global__ void dispatch_scatter() {
    int i = blockIdx.x * 256 + threadIdx.x;
    if (i < NSLOT) {
        int e = g_sel[i];
        int pos = atomicAdd(&g_pos[e], 1);
        g_list[pos] = i;
    }
}

// ---------------- tf32 tensor-core GEMM:  C[M,N] = A[M,K] @ B[N,K]^T ----------------
// 128x128 tile, BK=32, 256 threads (8 warps 4x2), warp tile 32x64 via m16n8k8.
// smem double-buffered; values pre-converted to tf32 at store; K-pairs (k,k+4)
// stored adjacent so fragment loads are conflict-free LDS.64.
__device__ __forceinline__ float f2tf32f(float x) {
    unsigned r;
    asm("cvt.rna.tf32.f32 %0, %1;" : "=r"(r) : "f"(x));
    return __uint_as_float(r);
}
__device__ __forceinline__ void mma_tf32(float* c, const unsigned* a, const unsigned* b) {
    asm volatile(
        "mma.sync.aligned.m16n8k8.row.col.f32.tf32.tf32.f32 "
        "{%0,%1,%2,%3}, {%4,%5,%6,%7}, {%8,%9}, {%0,%1,%2,%3};"
        : "+f"(c[0]), "+f"(c[1]), "+f"(c[2]), "+f"(c[3])
        : "r"(a[0]), "r"(a[1]), "r"(a[2]), "r"(a[3]), "r"(b[0]), "r"(b[1]));
}

#define GSTR 40                 // 32 + 8 pad: conflict-free LDS.64 fragments
#define GTILE (128 * GSTR)      // floats per matrix per stage
#define GEMM_SMEM (4 * GTILE * 4)  // bytes: 2 matrices x 2 stages

__global__ __launch_bounds__(256, 1)
void gemm_tf32_kernel(const float* __restrict__ A, const float* __restrict__ B,
                      float* __restrict__ C, int M, int N, int K) {
    extern __shared__ float sm[];
    int bm = blockIdx.y * 128, bn = blockIdx.x * 128;
    int tid = threadIdx.x;
    int lane = tid & 31, wid = tid >> 5;
    int wm = (wid >> 1) * 32, wn = (wid & 1) * 64;
    int g = lane >> 2, tg = lane & 3;

    float acc[2][8][4];
    #pragma unroll
    for (int mt = 0; mt < 2; mt++)
        #pragma unroll
        for (int nt = 0; nt < 8; nt++)
            #pragma unroll
            for (int i = 0; i < 4; i++) acc[mt][nt][i] = 0.f;

    float4 ra[4], rb[4];

    // prologue: global load tile 0
    #pragma unroll
    for (int l = 0; l < 4; l++) {
        int idx = tid * 4 + l;
        int row = idx >> 3, q = idx & 7;
        ra[l] = *(const float4*)(A + (size_t)(bm + row) * K + q * 4);
        rb[l] = *(const float4*)(B + (size_t)(bn + row) * K + q * 4);
    }
    // store tile 0 (stage 0), tf32-converted, permuted cols
    {
        float* As = sm;
        float* Bs = sm + GTILE;
        #pragma unroll
        for (int l = 0; l < 4; l++) {
            int idx = tid * 4 + l;
            int row = idx >> 3, q = idx & 7;
            int cb = (q >> 1) * 8 + (q & 1);
            float* ap = As + row * GSTR + cb;
            float* bp = Bs + row * GSTR + cb;
            ap[0] = f2tf32f(ra[l].x); ap[2] = f2tf32f(ra[l].y);
            ap[4] = f2tf32f(ra[l].z); ap[6] = f2tf32f(ra[l].w);
            bp[0] = f2tf32f(rb[l].x); bp[2] = f2tf32f(rb[l].y);
            bp[4] = f2tf32f(rb[l].z); bp[6] = f2tf32f(rb[l].w);
        }
    }
    __syncthreads();

    int ntiles = K / 32;
    for (int kt = 0; kt < ntiles; kt++) {
        int st = kt & 1;
        if (kt + 1 < ntiles) {
            int k0 = (kt + 1) * 32;
            #pragma unroll
            for (int l = 0; l < 4; l++) {
                int idx = tid * 4 + l;
                int row = idx >> 3, q = idx & 7;
                ra[l] = *(const float4*)(A + (size_t)(bm + row) * K + k0 + q * 4);
                rb[l] = *(const float4*)(B + (size_t)(bn + row) * K + k0 + q * 4);
            }
        }
        // compute on stage st
        {
            const float* As = sm + st * 2 * GTILE;
            const float* Bs = As + GTILE;
            #pragma unroll
            for (int kg = 0; kg < 4; kg++) {
                uint2 av[2][2], bv[8];
                #pragma unroll
                for (int mt = 0; mt < 2; mt++) {
                    av[mt][0] = *(const uint2*)&As[(wm + mt * 16 + g) * GSTR + kg * 8 + tg * 2];
                    av[mt][1] = *(const uint2*)&As[(wm + mt * 16 + g + 8) * GSTR + kg * 8 + tg * 2];
                }
                #pragma unroll
                for (int nt = 0; nt < 8; nt++)
                    bv[nt] = *(const uint2*)&Bs[(wn + nt * 8 + g) * GSTR + kg * 8 + tg * 2];
                #pragma unroll
                for (int mt = 0; mt < 2; mt++) {
                    unsigned af[4] = { av[mt][0].x, av[mt][1].x, av[mt][0].y, av[mt][1].y };
                    #pragma unroll
                    for (int nt = 0; nt < 8; nt++) {
                        unsigned bf[2] = { bv[nt].x, bv[nt].y };
                        mma_tf32(acc[mt][nt], af, bf);
                    }
                }
            }
        }
        if (kt + 1 < ntiles) {
            float* As = sm + (st ^ 1) * 2 * GTILE;
            float* Bs = As + GTILE;
            #pragma unroll
            for (int l = 0; l < 4; l++) {
                int idx = tid * 4 + l;
                int row = idx >> 3, q = idx & 7;
                int cb = (q >> 1) * 8 + (q & 1);
                float* ap = As + row * GSTR + cb;
                float* bp = Bs + row * GSTR + cb;
                ap[0] = f2tf32f(ra[l].x); ap[2] = f2tf32f(ra[l].y);
                ap[4] = f2tf32f(ra[l].z); ap[6] = f2tf32f(ra[l].w);
                bp[0] = f2tf32f(rb[l].x); bp[2] = f2tf32f(rb[l].y);
                bp[4] = f2tf32f(rb[l].z); bp[6] = f2tf32f(rb[l].w);
            }
            __syncthreads();
        }
    }

    // epilogue
    #pragma unroll
    for (int mt = 0; mt < 2; mt++) {
        #pragma unroll
        for (int nt = 0; nt < 8; nt++) {
            int r0 = bm + wm + mt * 16 + g;
            int c0 = bn + wn + nt * 8 + 2 * tg;
            C[(size_t)r0 * N + c0]           = acc[mt][nt][0];
            C[(size_t)r0 * N + c0 + 1]       = acc[mt][nt][1];
            C[(size_t)(r0 + 8) * N + c0]     = acc[mt][nt][2];
            C[(size_t)(r0 + 8) * N + c0 + 1] = acc[mt][nt][3];
        }
    }
}

// ---------------- grouped rank-16 down-projection ----------------
// Block handles 32 slots of one expert; A[e] K-chunk staged in smem (read once per 32 slots).
#define GL_G 32
#define GL_KC 128
__global__ __launch_bounds__(256)
void lora_in_grouped(const float* __restrict__ X, const float* __restrict__ Amat,
                     float* __restrict__ Tout, int K, int tok_row) {
    int e = blockIdx.y;
    int n_e = g_cnt[e];
    int base = blockIdx.x * GL_G;
    if (base >= n_e) return;
    __shared__ float As[R_DIM][GL_KC];
    __shared__ int sl[GL_G];
    int tid = threadIdx.x, lane = tid & 31, w = tid >> 5;
    if (tid < GL_G) {
        int j = base + tid;
        sl[tid] = (j < n_e) ? g_list[g_off[e] + j] : -1;
    }
    __syncthreads();
    int p[4];
    const float* xr[4];
    #pragma unroll
    for (int s = 0; s < 4; s++) {
        p[s] = sl[w * 4 + s];
        int row = (p[s] < 0) ? 0 : (tok_row ? (p[s] >> 1) : p[s]);
        xr[s] = X + (size_t)row * K;
    }
    float acc[4][R_DIM];
    #pragma unroll
    for (int s = 0; s < 4; s++)
        #pragma unroll
        for (int r = 0; r < R_DIM; r++) acc[s][r] = 0.f;

    const float* Ae = Amat + (size_t)e * R_DIM * K;
    for (int k0 = 0; k0 < K; k0 += GL_KC) {
        __syncthreads();
        #pragma unroll
        for (int l = 0; l < 2; l++) {
            int i = tid * 2 + l;
            int r = i >> 5, kq = i & 31;
            *(float4*)&As[r][kq * 4] = *(const float4*)(Ae + (size_t)r * K + k0 + kq * 4);
        }
        __syncthreads();
        float4 xv[4];
        #pragma unroll
        for (int s = 0; s < 4; s++) xv[s] = *(const float4*)(xr[s] + k0 + lane * 4);
        #pragma unroll
        for (int r = 0; r < R_DIM; r++) {
            float4 a4 = *(const float4*)&As[r][lane * 4];
            #pragma unroll
            for (int s = 0; s < 4; s++)
                acc[s][r] += xv[s].x * a4.x + xv[s].y * a4.y + xv[s].z * a4.z + xv[s].w * a4.w;
        }
    }
    #pragma unroll
    for (int s = 0; s < 4; s++) {
        #pragma unroll
        for (int r = 0; r < R_DIM; r++) {
            float v = acc[s][r];
            v += __shfl_xor_sync(0xffffffffu, v, 16);
            v += __shfl_xor_sync(0xffffffffu, v, 8);
            v += __shfl_xor_sync(0xffffffffu, v, 4);
            v += __shfl_xor_sync(0xffffffffu, v, 2);
            v += __shfl_xor_sync(0xffffffffu, v, 1);
            if (lane == 0 && p[s] >= 0) Tout[p[s] * R_DIM + r] = v;
        }
    }
}

// ---------------- grouped fc1 epilogue: 16 slots per block share B1 row reads ----------------
#define GA_G 16
__global__ __launch_bounds__(256)
void act_grouped(const float* __restrict__ B1mat, const float* __restrict__ b1) {
    int e = blockIdx.y;
    int n_e = g_cnt[e];
    int base = blockIdx.x * GA_G;
    if (base >= n_e) return;
    int cnt = min(GA_G, n_e - base);
    __shared__ float t1s[GA_G][R_DIM];
    __shared__ int sl[GA_G];
    int tid = threadIdx.x;
    if (tid < GA_G) sl[tid] = (tid < cnt) ? g_list[g_off[e] + base + tid] : -1;
    __syncthreads();
    if (tid < GA_G * R_DIM) {
        int s = tid >> 4, r = tid & 15;
        int ps = sl[s];
        t1s[s][r] = (ps >= 0) ? g_t1[ps * R_DIM + r] : 0.f;
    }
    __syncthreads();
    const float* B1e = B1mat + (size_t)e * H_DIM * R_DIM;
    for (int h = tid; h < H_DIM; h += 256) {
        const float4* br = (const float4*)(B1e + (size_t)h * R_DIM);
        float4 v0 = br[0], v1 = br[1], v2 = br[2], v3 = br[3];
        float bb = b1[h];
        #pragma unroll
        for (int s = 0; s < GA_G; s++) {
            int ps = sl[s];
            if (ps >= 0) {
                float lor = v0.x * t1s[s][0]  + v0.y * t1s[s][1]  + v0.z * t1s[s][2]  + v0.w * t1s[s][3]
                          + v1.x * t1s[s][4]  + v1.y * t1s[s][5]  + v1.z * t1s[s][6]  + v1.w * t1s[s][7]
                          + v2.x * t1s[s][8]  + v2.y * t1s[s][9]  + v2.z * t1s[s][10] + v2.w * t1s[s][11]
                          + v3.x * t1s[s][12] + v3.y * t1s[s][13] + v3.z * t1s[s][14] + v3.w * t1s[s][15];
                float val = g_common[(size_t)(ps >> 1) * H_DIM + h] + bb + LSCALE * lor;
                g_act[(size_t)ps * H_DIM + h] = val / (1.f + expf(-val));
            }
        }
    }
}

// ---------------- combine ----------------
__global__ void combine_kernel(const float* __restrict__ B2mat, const float* __restrict__ b2,
                               float* __restrict__ out) {
    int t = blockIdx.x;
    __shared__ float t2s[2][R_DIM];
    __shared__ float wsh[2];
    __shared__ int esh[2];
    if (threadIdx.x < 2 * R_DIM) t2s[threadIdx.x >> 4][threadIdx.x & 15] = g_t2[t * 2 * R_DIM + threadIdx.x];
    if (threadIdx.x < 2) { wsh[threadIdx.x] = g_wt[t * 2 + threadIdx.x]; esh[threadIdx.x] = g_sel[t * 2 + threadIdx.x]; }
    __syncthreads();
    for (int d = threadIdx.x; d < D_DIM; d += blockDim.x) {
        float val = 0.f;
        #pragma unroll
        for (int k = 0; k < 2; k++) {
            const float4* br = (const float4*)(B2mat + ((size_t)esh[k] * D_DIM + d) * R_DIM);
            float lor = 0.f;
            #pragma unroll
            for (int q = 0; q < 4; q++) {
                float4 v = br[q];
                lor += v.x * t2s[k][q * 4 + 0] + v.y * t2s[k][q * 4 + 1]
                     + v.z * t2s[k][q * 4 + 2] + v.w * t2s[k][q * 4 + 3];
            }
            val += wsh[k] * (g_base2[((size_t)t * 2 + k) * D_DIM + d] + b2[d] + LSCALE * lor);
        }
        out[(size_t)t * D_DIM + d] = val;
    }
}

// ---------------- launch ----------------
extern "C" void kernel_launch(void* const* d_in, const int* in_sizes, int n_in,
                              void* d_out, int out_size) {
    const float* x    = (const float*)d_in[0];
    const float* gate = (const float*)d_in[1];
    const float* W1   = (const float*)d_in[2];
    const float* b1   = (const float*)d_in[3];
    const float* W2   = (const float*)d_in[4];
    const float* b2   = (const float*)d_in[5];
    const float* A1   = (const float*)d_in[6];
    const float* B1   = (const float*)d_in[7];
    const float* A2   = (const float*)d_in[8];
    const float* B2   = (const float*)d_in[9];
    float* out = (float*)d_out;

    float *p_common, *p_act, *p_base2, *p_t1, *p_t2;
    cudaGetSymbolAddress((void**)&p_common, g_common);
    cudaGetSymbolAddress((void**)&p_act,    g_act);
    cudaGetSymbolAddress((void**)&p_base2,  g_base2);
    cudaGetSymbolAddress((void**)&p_t1,     g_t1);
    cudaGetSymbolAddress((void**)&p_t2,     g_t2);

    cudaFuncSetAttribute(gemm_tf32_kernel,
                         cudaFuncAttributeMaxDynamicSharedMemorySize, GEMM_SMEM);

    // 1. router
    router_kernel<<<N_TOK, 256>>>(x, gate);

    // 2. expert-grouped dispatch
    dispatch_zero<<<1, 32>>>();
    dispatch_count<<<NSLOT / 256, 256>>>();
    dispatch_prefix<<<1, 32>>>();
    dispatch_scatter<<<NSLOT / 256, 256>>>();

    // 3. common_fc1 = X @ W1^T
    {
        dim3 grid(H_DIM / 128, N_TOK / 128);
        gemm_tf32_kernel<<<grid, 256, GEMM_SMEM>>>(x, W1, p_common, N_TOK, H_DIM, D_DIM);
    }

    // 4. t1 = x @ A1[e]^T (grouped by expert)
    lora_in_grouped<<<dim3(NSLOT / GL_G, E_NUM), 256>>>(x, A1, p_t1, D_DIM, 1);

    // 5. a = silu(common + b1 + scale * t1 @ B1[e]^T) (grouped)
    act_grouped<<<dim3(NSLOT / GA_G, E_NUM), 256>>>(B1, b1);

    // 6. base2 = a @ W2^T
    {
        dim3 grid(D_DIM / 128, NSLOT / 128);
        gemm_tf32_kernel<<<grid, 256, GEMM_SMEM>>>(p_act, W2, p_base2, NSLOT, D_DIM, H_DIM);
    }

    // 7. t2 = a @ A2[e]^T (grouped)
    lora_in_grouped<<<dim3(NSLOT / GL_G, E_NUM), 256>>>(p_act, A2, p_t2, H_DIM, 0);

    // 8. out = sum_k w_k * (base2 + b2 + scale * t2 @ B2[e]^T)
    combine_kernel<<<N_TOK, 256>>>(B2, b2, out);
}

// round 5
// speedup vs baseline: 1.3043x; 1.3043x over previous
#include <cuda_runtime.h>
#include <math.h>

#define N_TOK 2048
#define D_DIM 1024
#define H_DIM 4096
#define E_NUM 8
#define R_DIM 16
#define LSCALE 2.0f   // lora_alpha / lora_r = 32/16
#define NSLOT (2*N_TOK)

// ---------------- scratch (device globals; no allocation allowed) ----------------
__device__ float g_common[N_TOK * H_DIM];
__device__ float g_act[NSLOT * H_DIM];
__device__ float g_base2[NSLOT * D_DIM];
__device__ float g_t1[NSLOT * R_DIM];
__device__ float g_t2[NSLOT * R_DIM];
__device__ int   g_sel[NSLOT];
__device__ float g_wt[NSLOT];
// expert-grouped dispatch
__device__ int g_cnt[E_NUM];
__device__ int g_off[E_NUM];
__device__ int g_pos[E_NUM];
__device__ int g_list[NSLOT];

// ---------------- router ----------------
__global__ void router_kernel(const float* __restrict__ x, const float* __restrict__ gate) {
    int t = blockIdx.x;
    int warp = threadIdx.x >> 5, lane = threadIdx.x & 31;
    __shared__ float logits[E_NUM];
    const float4* xr = (const float4*)(x + (size_t)t * D_DIM);
    const float4* gr = (const float4*)(gate + (size_t)warp * D_DIM);
    float s = 0.f;
    for (int i = lane; i < D_DIM / 4; i += 32) {
        float4 a = xr[i], b = gr[i];
        s += a.x * b.x + a.y * b.y + a.z * b.z + a.w * b.w;
    }
    #pragma unroll
    for (int o = 16; o; o >>= 1) s += __shfl_xor_sync(0xffffffffu, s, o);
    if (lane == 0) logits[warp] = s;
    __syncthreads();
    if (threadIdx.x == 0) {
        float best = -1e30f; int i0 = 0;
        #pragma unroll
        for (int e = 0; e < E_NUM; e++) if (logits[e] > best) { best = logits[e]; i0 = e; }
        float best2 = -1e30f; int i1 = 0;
        #pragma unroll
        for (int e = 0; e < E_NUM; e++) if (e != i0 && logits[e] > best2) { best2 = logits[e]; i1 = e; }
        float p1 = expf(best2 - best);
        float inv = 1.f / (1.f + p1);
        g_sel[t * 2 + 0] = i0; g_sel[t * 2 + 1] = i1;
        g_wt[t * 2 + 0] = inv; g_wt[t * 2 + 1] = p1 * inv;
    }
}

// ---------------- dispatch: count / prefix / scatter ----------------
__global__ void dispatch_zero() {
    if (threadIdx.x < E_NUM) g_cnt[threadIdx.x] = 0;
}
__global__ void dispatch_count() {
    int i = blockIdx.x * 256 + threadIdx.x;
    if (i < NSLOT) atomicAdd(&g_cnt[g_sel[i]], 1);
}
__global__ void dispatch_prefix() {
    if (threadIdx.x == 0) {
        int o = 0;
        for (int e = 0; e < E_NUM; e++) { g_off[e] = o; g_pos[e] = o; o += g_cnt[e]; }
    }
}
__global__ void dispatch_scatter() {
    int i = blockIdx.x * 256 + threadIdx.x;
    if (i < NSLOT) {
        int e = g_sel[i];
        int pos = atomicAdd(&g_pos[e], 1);
        g_list[pos] = i;
    }
}

// ---------------- tf32 tensor-core GEMM (R3 version):  C[M,N] = A[M,K] @ B[N,K]^T ----------------
// 128x128 tile, BK=32, 256 threads (8 warps, 4x2), warp tile 32x64 via m16n8k8.
// Static 36KB smem -> 2 CTAs/SM (16 warps) for latency hiding.
__device__ __forceinline__ unsigned f2tf32(float x) {
    unsigned r;
    asm("cvt.rna.tf32.f32 %0, %1;" : "=r"(r) : "f"(x));
    return r;
}

__device__ __forceinline__ void mma_tf32(float* c, const unsigned* a, const unsigned* b) {
    asm volatile(
        "mma.sync.aligned.m16n8k8.row.col.f32.tf32.tf32.f32 "
        "{%0,%1,%2,%3}, {%4,%5,%6,%7}, {%8,%9}, {%0,%1,%2,%3};"
        : "+f"(c[0]), "+f"(c[1]), "+f"(c[2]), "+f"(c[3])
        : "r"(a[0]), "r"(a[1]), "r"(a[2]), "r"(a[3]), "r"(b[0]), "r"(b[1]));
}

#define GLDS 36   // BK(32) + 4 pad

__global__ __launch_bounds__(256)
void gemm_tf32_kernel(const float* __restrict__ A, const float* __restrict__ B,
                      float* __restrict__ C, int M, int N, int K) {
    const int BM = 128, BN = 128, BK = 32;
    __shared__ float As[BM * GLDS];
    __shared__ float Bs[BN * GLDS];
    int bm = blockIdx.y * BM, bn = blockIdx.x * BN;
    int tid = threadIdx.x;
    int lane = tid & 31;
    int wid = tid >> 5;
    int wm = (wid >> 1) * 32;
    int wn = (wid & 1) * 64;
    int g = lane >> 2, tg = lane & 3;

    float acc[2][8][4];
    #pragma unroll
    for (int mt = 0; mt < 2; mt++)
        #pragma unroll
        for (int nt = 0; nt < 8; nt++)
            #pragma unroll
            for (int i = 0; i < 4; i++) acc[mt][nt][i] = 0.f;

    float4 ra[4], rb[4];

    // prologue: load K-tile 0
    #pragma unroll
    for (int l = 0; l < 4; l++) {
        int idx = tid * 4 + l;
        int row = idx >> 3, q = idx & 7;
        ra[l] = *(const float4*)(A + (size_t)(bm + row) * K + q * 4);
        rb[l] = *(const float4*)(B + (size_t)(bn + row) * K + q * 4);
    }
    #pragma unroll
    for (int l = 0; l < 4; l++) {
        int idx = tid * 4 + l;
        int row = idx >> 3, q = idx & 7;
        *(float4*)&As[row * GLDS + q * 4] = ra[l];
        *(float4*)&Bs[row * GLDS + q * 4] = rb[l];
    }
    __syncthreads();

    for (int k0 = 0; k0 < K; k0 += BK) {
        bool more = (k0 + BK) < K;
        if (more) {
            #pragma unroll
            for (int l = 0; l < 4; l++) {
                int idx = tid * 4 + l;
                int row = idx >> 3, q = idx & 7;
                ra[l] = *(const float4*)(A + (size_t)(bm + row) * K + k0 + BK + q * 4);
                rb[l] = *(const float4*)(B + (size_t)(bn + row) * K + k0 + BK + q * 4);
            }
        }
        #pragma unroll
        for (int ks = 0; ks < BK; ks += 8) {
            unsigned af[2][4];
            unsigned bf[8][2];
            #pragma unroll
            for (int mt = 0; mt < 2; mt++) {
                int rbse = wm + mt * 16;
                af[mt][0] = f2tf32(As[(rbse + g) * GLDS + ks + tg]);
                af[mt][1] = f2tf32(As[(rbse + g + 8) * GLDS + ks + tg]);
                af[mt][2] = f2tf32(As[(rbse + g) * GLDS + ks + tg + 4]);
                af[mt][3] = f2tf32(As[(rbse + g + 8) * GLDS + ks + tg + 4]);
            }
            #pragma unroll
            for (int nt = 0; nt < 8; nt++) {
                int cb = wn + nt * 8;
                bf[nt][0] = f2tf32(Bs[(cb + g) * GLDS + ks + tg]);
                bf[nt][1] = f2tf32(Bs[(cb + g) * GLDS + ks + tg + 4]);
            }
            #pragma unroll
            for (int mt = 0; mt < 2; mt++)
                #pragma unroll
                for (int nt = 0; nt < 8; nt++)
                    mma_tf32(acc[mt][nt], af[mt], bf[nt]);
        }
        __syncthreads();
        if (more) {
            #pragma unroll
            for (int l = 0; l < 4; l++) {
                int idx = tid * 4 + l;
                int row = idx >> 3, q = idx & 7;
                *(float4*)&As[row * GLDS + q * 4] = ra[l];
                *(float4*)&Bs[row * GLDS + q * 4] = rb[l];
            }
            __syncthreads();
        }
    }

    // epilogue
    #pragma unroll
    for (int mt = 0; mt < 2; mt++) {
        #pragma unroll
        for (int nt = 0; nt < 8; nt++) {
            int r0 = bm + wm + mt * 16 + g;
            int c0 = bn + wn + nt * 8 + 2 * tg;
            C[(size_t)r0 * N + c0]           = acc[mt][nt][0];
            C[(size_t)r0 * N + c0 + 1]       = acc[mt][nt][1];
            C[(size_t)(r0 + 8) * N + c0]     = acc[mt][nt][2];
            C[(size_t)(r0 + 8) * N + c0 + 1] = acc[mt][nt][3];
        }
    }
}

// ---------------- grouped rank-16 down-projection ----------------
#define GL_G 32
#define GL_KC 128
__global__ __launch_bounds__(256)
void lora_in_grouped(const float* __restrict__ X, const float* __restrict__ Amat,
                     float* __restrict__ Tout, int K, int tok_row) {
    int e = blockIdx.y;
    int n_e = g_cnt[e];
    int base = blockIdx.x * GL_G;
    if (base >= n_e) return;
    __shared__ float As[R_DIM][GL_KC];
    __shared__ int sl[GL_G];
    int tid = threadIdx.x, lane = tid & 31, w = tid >> 5;
    if (tid < GL_G) {
        int j = base + tid;
        sl[tid] = (j < n_e) ? g_list[g_off[e] + j] : -1;
    }
    __syncthreads();
    int p[4];
    const float* xr[4];
    #pragma unroll
    for (int s = 0; s < 4; s++) {
        p[s] = sl[w * 4 + s];
        int row = (p[s] < 0) ? 0 : (tok_row ? (p[s] >> 1) : p[s]);
        xr[s] = X + (size_t)row * K;
    }
    float acc[4][R_DIM];
    #pragma unroll
    for (int s = 0; s < 4; s++)
        #pragma unroll
        for (int r = 0; r < R_DIM; r++) acc[s][r] = 0.f;

    const float* Ae = Amat + (size_t)e * R_DIM * K;
    for (int k0 = 0; k0 < K; k0 += GL_KC) {
        __syncthreads();
        #pragma unroll
        for (int l = 0; l < 2; l++) {
            int i = tid * 2 + l;
            int r = i >> 5, kq = i & 31;
            *(float4*)&As[r][kq * 4] = *(const float4*)(Ae + (size_t)r * K + k0 + kq * 4);
        }
        __syncthreads();
        float4 xv[4];
        #pragma unroll
        for (int s = 0; s < 4; s++) xv[s] = *(const float4*)(xr[s] + k0 + lane * 4);
        #pragma unroll
        for (int r = 0; r < R_DIM; r++) {
            float4 a4 = *(const float4*)&As[r][lane * 4];
            #pragma unroll
            for (int s = 0; s < 4; s++)
                acc[s][r] += xv[s].x * a4.x + xv[s].y * a4.y + xv[s].z * a4.z + xv[s].w * a4.w;
        }
    }
    #pragma unroll
    for (int s = 0; s < 4; s++) {
        #pragma unroll
        for (int r = 0; r < R_DIM; r++) {
            float v = acc[s][r];
            v += __shfl_xor_sync(0xffffffffu, v, 16);
            v += __shfl_xor_sync(0xffffffffu, v, 8);
            v += __shfl_xor_sync(0xffffffffu, v, 4);
            v += __shfl_xor_sync(0xffffffffu, v, 2);
            v += __shfl_xor_sync(0xffffffffu, v, 1);
            if (lane == 0 && p[s] >= 0) Tout[p[s] * R_DIM + r] = v;
        }
    }
}

// ---------------- grouped fc1 epilogue ----------------
#define GA_G 16
__global__ __launch_bounds__(256)
void act_grouped(const float* __restrict__ B1mat, const float* __restrict__ b1) {
    int e = blockIdx.y;
    int n_e = g_cnt[e];
    int base = blockIdx.x * GA_G;
    if (base >= n_e) return;
    int cnt = min(GA_G, n_e - base);
    __shared__ float t1s[GA_G][R_DIM];
    __shared__ int sl[GA_G];
    int tid = threadIdx.x;
    if (tid < GA_G) sl[tid] = (tid < cnt) ? g_list[g_off[e] + base + tid] : -1;
    __syncthreads();
    if (tid < GA_G * R_DIM) {
        int s = tid >> 4, r = tid & 15;
        int ps = sl[s];
        t1s[s][r] = (ps >= 0) ? g_t1[ps * R_DIM + r] : 0.f;
    }
    __syncthreads();
    const float* B1e = B1mat + (size_t)e * H_DIM * R_DIM;
    for (int h = tid; h < H_DIM; h += 256) {
        const float4* br = (const float4*)(B1e + (size_t)h * R_DIM);
        float4 v0 = br[0], v1 = br[1], v2 = br[2], v3 = br[3];
        float bb = b1[h];
        #pragma unroll
        for (int s = 0; s < GA_G; s++) {
            int ps = sl[s];
            if (ps >= 0) {
                float lor = v0.x * t1s[s][0]  + v0.y * t1s[s][1]  + v0.z * t1s[s][2]  + v0.w * t1s[s][3]
                          + v1.x * t1s[s][4]  + v1.y * t1s[s][5]  + v1.z * t1s[s][6]  + v1.w * t1s[s][7]
                          + v2.x * t1s[s][8]  + v2.y * t1s[s][9]  + v2.z * t1s[s][10] + v2.w * t1s[s][11]
                          + v3.x * t1s[s][12] + v3.y * t1s[s][13] + v3.z * t1s[s][14] + v3.w * t1s[s][15];
                float val = g_common[(size_t)(ps >> 1) * H_DIM + h] + bb + LSCALE * lor;
                g_act[(size_t)ps * H_DIM + h] = val / (1.f + expf(-val));
            }
        }
    }
}

// ---------------- combine ----------------
__global__ void combine_kernel(const float* __restrict__ B2mat, const float* __restrict__ b2,
                               float* __restrict__ out) {
    int t = blockIdx.x;
    __shared__ float t2s[2][R_DIM];
    __shared__ float wsh[2];
    __shared__ int esh[2];
    if (threadIdx.x < 2 * R_DIM) t2s[threadIdx.x >> 4][threadIdx.x & 15] = g_t2[t * 2 * R_DIM + threadIdx.x];
    if (threadIdx.x < 2) { wsh[threadIdx.x] = g_wt[t * 2 + threadIdx.x]; esh[threadIdx.x] = g_sel[t * 2 + threadIdx.x]; }
    __syncthreads();
    for (int d = threadIdx.x; d < D_DIM; d += blockDim.x) {
        float val = 0.f;
        #pragma unroll
        for (int k = 0; k < 2; k++) {
            const float4* br = (const float4*)(B2mat + ((size_t)esh[k] * D_DIM + d) * R_DIM);
            float lor = 0.f;
            #pragma unroll
            for (int q = 0; q < 4; q++) {
                float4 v = br[q];
                lor += v.x * t2s[k][q * 4 + 0] + v.y * t2s[k][q * 4 + 1]
                     + v.z * t2s[k][q * 4 + 2] + v.w * t2s[k][q * 4 + 3];
            }
            val += wsh[k] * (g_base2[((size_t)t * 2 + k) * D_DIM + d] + b2[d] + LSCALE * lor);
        }
        out[(size_t)t * D_DIM + d] = val;
    }
}

// ---------------- launch ----------------
extern "C" void kernel_launch(void* const* d_in, const int* in_sizes, int n_in,
                              void* d_out, int out_size) {
    const float* x    = (const float*)d_in[0];
    const float* gate = (const float*)d_in[1];
    const float* W1   = (const float*)d_in[2];
    const float* b1   = (const float*)d_in[3];
    const float* W2   = (const float*)d_in[4];
    const float* b2   = (const float*)d_in[5];
    const float* A1   = (const float*)d_in[6];
    const float* B1   = (const float*)d_in[7];
    const float* A2   = (const float*)d_in[8];
    const float* B2   = (const float*)d_in[9];
    float* out = (float*)d_out;

    float *p_common, *p_act, *p_base2, *p_t1, *p_t2;
    cudaGetSymbolAddress((void**)&p_common, g_common);
    cudaGetSymbolAddress((void**)&p_act,    g_act);
    cudaGetSymbolAddress((void**)&p_base2,  g_base2);
    cudaGetSymbolAddress((void**)&p_t1,     g_t1);
    cudaGetSymbolAddress((void**)&p_t2,     g_t2);

    // 1. router
    router_kernel<<<N_TOK, 256>>>(x, gate);

    // 2. expert-grouped dispatch
    dispatch_zero<<<1, 32>>>();
    dispatch_count<<<NSLOT / 256, 256>>>();
    dispatch_prefix<<<1, 32>>>();
    dispatch_scatter<<<NSLOT / 256, 256>>>();

    // 3. common_fc1 = X @ W1^T
    {
        dim3 grid(H_DIM / 128, N_TOK / 128);
        gemm_tf32_kernel<<<grid, 256>>>(x, W1, p_common, N_TOK, H_DIM, D_DIM);
    }

    // 4. t1 = x @ A1[e]^T (grouped by expert)
    lora_in_grouped<<<dim3(NSLOT / GL_G, E_NUM), 256>>>(x, A1, p_t1, D_DIM, 1);

    // 5. a = silu(common + b1 + scale * t1 @ B1[e]^T) (grouped)
    act_grouped<<<dim3(NSLOT / GA_G, E_NUM), 256>>>(B1, b1);

    // 6. base2 = a @ W2^T
    {
        dim3 grid(D_DIM / 128, NSLOT / 128);
        gemm_tf32_kernel<<<grid, 256>>>(p_act, W2, p_base2, NSLOT, D_DIM, H_DIM);
    }

    // 7. t2 = a @ A2[e]^T (grouped)
    lora_in_grouped<<<dim3(NSLOT / GL_G, E_NUM), 256>>>(p_act, A2, p_t2, H_DIM, 0);

    // 8. out = sum_k w_k * (base2 + b2 + scale * t2 @ B2[e]^T)
    combine_kernel<<<N_TOK, 256>>>(B2, b2, out);
}